// round 3
// baseline (speedup 1.0000x reference)
#include <cuda_runtime.h>
#include <cuda_bf16.h>
#include <math_constants.h>

// Piecewise-linear LUT (65-knot uniform grid [-8,8], h=0.25), exact
// searchsorted(side='right') semantics via analytic index + one-step fixup
// against the actual table knot values.
//
// Per element: ONE LDS.128 (extended segment record {x_lo, x_hi, a, b}) +
// one FMA. Out-of-range and the reference's "+1 for x >= xs[63]" quirk are
// folded into sentinel/last records, so there is no separate branch math.

#define NPTS 65
#define NSEG 64
#define NREC 66   // records indexed by (segment_idx + 1), idx in [-1, 64]

__device__ __forceinline__ float eval_rec(float xv, const float4* __restrict__ s_rec)
{
    // Analytic estimate of idx+1 on the uniform grid: floor(4x + 32) + 1.
    int j = __float2int_rd(fmaf(xv, 4.0f, 32.0f)) + 1;
    j = max(0, min(j, NREC - 1));

    float4 r = s_rec[j];
    // One-step fixup vs actual knot values (rec.x = x_lo, rec.y = x_hi).
    if (xv < r.x)       r = s_rec[j - 1];
    else if (xv >= r.y) r = s_rec[j + 1];

    return fmaf(r.z, xv, r.w);   // a*x + b
}

__device__ __forceinline__ void build_records(const float* __restrict__ table,
                                              float* s_xs, float* s_ys,
                                              float4* s_rec, int t)
{
    if (t < NPTS) {
        s_xs[t] = table[2 * t + 0];
        s_ys[t] = table[2 * t + 1];
    }
    __syncthreads();
    if (t < NREC) {
        float4 r;
        if (t == 0) {
            r = make_float4(-CUDART_INF_F, s_xs[0], 0.0f, 0.0f);
        } else if (t == NREC - 1) {
            r = make_float4(s_xs[NPTS - 1], CUDART_INF_F, 0.0f, 1.0f);
        } else {
            int k = t - 1;  // segment index 0..63
            float a = (s_ys[k + 1] - s_ys[k]) / (s_xs[k + 1] - s_xs[k]);
            float b = s_ys[k] - a * s_xs[k];
            if (k == NSEG - 1) b += 1.0f;  // fold "+1 for x >= xs[63]" quirk
            r = make_float4(s_xs[k], s_xs[k + 1], a, b);
        }
        s_rec[t] = r;
    }
    __syncthreads();
}

__global__ void __launch_bounds__(256)
cSigmoid_pwl_kernel(const float4* __restrict__ x4,
                    const float*  __restrict__ table,
                    float4* __restrict__ out4,
                    int n4)
{
    __shared__ float  s_xs[NPTS];
    __shared__ float  s_ys[NPTS];
    __shared__ float4 s_rec[NREC];

    int t = threadIdx.x;
    build_records(table, s_xs, s_ys, s_rec, t);

    int i = blockIdx.x * blockDim.x + t;
    if (i >= n4) return;

    float4 v = x4[i];
    float4 r;
    r.x = eval_rec(v.x, s_rec);
    r.y = eval_rec(v.y, s_rec);
    r.z = eval_rec(v.z, s_rec);
    r.w = eval_rec(v.w, s_rec);
    out4[i] = r;
}

// Scalar tail (n % 4 != 0); not hit for this shape but kept for generality.
__global__ void cSigmoid_pwl_tail_kernel(const float* __restrict__ x,
                                         const float* __restrict__ table,
                                         float* __restrict__ out,
                                         int start, int n)
{
    __shared__ float  s_xs[NPTS];
    __shared__ float  s_ys[NPTS];
    __shared__ float4 s_rec[NREC];

    int t = threadIdx.x;
    build_records(table, s_xs, s_ys, s_rec, t);

    int i = start + blockIdx.x * blockDim.x + t;
    if (i < n) out[i] = eval_rec(x[i], s_rec);
}

extern "C" void kernel_launch(void* const* d_in, const int* in_sizes, int n_in,
                              void* d_out, int out_size)
{
    const float* x     = (const float*)d_in[0];
    const float* table = (const float*)d_in[1];
    float* out         = (float*)d_out;

    int n  = in_sizes[0];
    int n4 = n / 4;

    if (n4 > 0) {
        int threads = 256;
        int blocks  = (n4 + threads - 1) / threads;
        cSigmoid_pwl_kernel<<<blocks, threads>>>(
            (const float4*)x, table, (float4*)out, n4);
    }

    int tail = n - n4 * 4;
    if (tail > 0) {
        cSigmoid_pwl_tail_kernel<<<1, 256>>>(x, table, out, n4 * 4, n);
    }
}

// round 4
// speedup vs baseline: 1.5045x; 1.5045x over previous
#include <cuda_runtime.h>
#include <cuda_bf16.h>

// Piecewise-linear LUT (65 knots, uniform grid [-8,8], h=0.25).
// Exact searchsorted(side='right') semantics:
//   analytic index floor(fma(x,4,32)) + one-step fixup against the exact
//   arithmetic knot values 0.25k - 8 (all fp32-exact, identical to linspace).
// Per element: ~8 ALU + ONE conflict-free LDS.64 (per-lane-replicated (a,b)
// table) + 1 FMA. Out-of-range and the "+1 for x >= xs[63]" reference quirk
// are folded into sentinel records 0 and 65 / record 64's intercept.

#define NPTS 65
#define NSEG 64
#define NREC 66   // record j covers segment j-1; j=0 below-range, j=65 above

__device__ __forceinline__ float eval_rec(float xv,
                                          const float2* __restrict__ s_ab,
                                          int lane)
{
    // j0 = floor((x+8)*4)  (segment index, may be off by one from rounding)
    int j0 = __float2int_rd(fmaf(xv, 4.0f, 32.0f));
    // Fixup vs exact knots knot(k) = 0.25k - 8 (fp32-exact on this grid).
    float lo = fmaf((float)j0,       0.25f, -8.0f);
    float hi = fmaf((float)(j0 + 1), 0.25f, -8.0f);
    j0 += (xv >= hi) ? 1 : 0;
    j0 -= (xv <  lo) ? 1 : 0;
    int j = min(max(j0 + 1, 0), NREC - 1);   // record index in [0,65]

    float2 ab = s_ab[(j << 5) + lane];        // conflict-free: lane-private bank pair
    return fmaf(ab.x, xv, ab.y);
}

__device__ __forceinline__ void build_table(const float* __restrict__ table,
                                            float* s_xs, float* s_ys,
                                            float2* s_ab0, float2* s_ab, int t)
{
    if (t < NPTS) {
        s_xs[t] = table[2 * t + 0];
        s_ys[t] = table[2 * t + 1];
    }
    __syncthreads();
    if (t < NREC) {
        float a, b;
        if (t == 0)             { a = 0.0f; b = 0.0f; }   // x < xs[0]
        else if (t == NREC - 1) { a = 0.0f; b = 1.0f; }   // x >= xs[64]
        else {
            int k = t - 1;                                 // segment 0..63
            a = (s_ys[k + 1] - s_ys[k]) / (s_xs[k + 1] - s_xs[k]);
            b = s_ys[k] - a * s_xs[k];
            if (k == NSEG - 1) b += 1.0f;  // fold "+1 for x >= xs[63]"
        }
        s_ab0[t] = make_float2(a, b);
    }
    __syncthreads();
    for (int i = t; i < NREC * 32; i += blockDim.x)
        s_ab[i] = s_ab0[i >> 5];
    __syncthreads();
}

__device__ __forceinline__ float4 eval4(float4 v, const float2* s_ab, int lane)
{
    float4 r;
    r.x = eval_rec(v.x, s_ab, lane);
    r.y = eval_rec(v.y, s_ab, lane);
    r.z = eval_rec(v.z, s_ab, lane);
    r.w = eval_rec(v.w, s_ab, lane);
    return r;
}

// Each block handles 512 float4s (256 threads x 2).
__global__ void __launch_bounds__(256)
cSigmoid_pwl_kernel(const float4* __restrict__ x4,
                    const float*  __restrict__ table,
                    float4* __restrict__ out4,
                    int n4)
{
    __shared__ float  s_xs[NPTS];
    __shared__ float  s_ys[NPTS];
    __shared__ float2 s_ab0[NREC];
    __shared__ float2 s_ab[NREC * 32];

    int t = threadIdx.x;
    build_table(table, s_xs, s_ys, s_ab0, s_ab, t);

    int lane = t & 31;
    int base = blockIdx.x * 512;
    int i0 = base + t;
    int i1 = i0 + 256;

    // Two independent load->eval->store chains for MLP.
    if (i1 < n4) {
        float4 v0 = x4[i0];
        float4 v1 = x4[i1];
        out4[i0] = eval4(v0, s_ab, lane);
        out4[i1] = eval4(v1, s_ab, lane);
    } else if (i0 < n4) {
        float4 v0 = x4[i0];
        out4[i0] = eval4(v0, s_ab, lane);
    }
}

// Scalar tail (n % 4 != 0); not hit for this shape but kept for generality.
__global__ void cSigmoid_pwl_tail_kernel(const float* __restrict__ x,
                                         const float* __restrict__ table,
                                         float* __restrict__ out,
                                         int start, int n)
{
    __shared__ float  s_xs[NPTS];
    __shared__ float  s_ys[NPTS];
    __shared__ float2 s_ab0[NREC];
    __shared__ float2 s_ab[NREC * 32];

    int t = threadIdx.x;
    build_table(table, s_xs, s_ys, s_ab0, s_ab, t);

    int i = start + blockIdx.x * blockDim.x + t;
    if (i < n) out[i] = eval_rec(x[i], s_ab, t & 31);
}

extern "C" void kernel_launch(void* const* d_in, const int* in_sizes, int n_in,
                              void* d_out, int out_size)
{
    const float* x     = (const float*)d_in[0];
    const float* table = (const float*)d_in[1];
    float* out         = (float*)d_out;

    int n  = in_sizes[0];
    int n4 = n / 4;

    if (n4 > 0) {
        int blocks = (n4 + 511) / 512;
        cSigmoid_pwl_kernel<<<blocks, 256>>>(
            (const float4*)x, table, (float4*)out, n4);
    }

    int tail = n - n4 * 4;
    if (tail > 0) {
        cSigmoid_pwl_tail_kernel<<<1, 256>>>(x, table, out, n4 * 4, n);
    }
}

// round 5
// speedup vs baseline: 1.6797x; 1.1165x over previous
#include <cuda_runtime.h>
#include <cuda_bf16.h>

// Piecewise-linear LUT (65 knots, uniform grid [-8,8], h=0.25).
// Exact searchsorted(side='right') index with NO fixup:
//   idx = floor(4x + 32) = floor(4x) + 32, and 4*x is EXACT in fp32
//   (power-of-two multiply), so __float2int_rd(4x) + 32 is the exact index.
// Per element: FMUL + F2I + 2*IMNMX + IMAD + conflict-free LDS.64 + FFMA.
// Out-of-range and the reference's "+1 for x >= xs[63]" quirk live in
// sentinel records 0 / 65 and record 64's intercept.

#define NPTS 65
#define NSEG 64
#define NREC 66   // record j covers segment j-1; j=0 below-range, j=65 above

__device__ __forceinline__ float eval_rec(float xv,
                                          const float2* __restrict__ p_lane)
{
    // i = floor(4x), exact. Record index = i + 33, clamped to [0, 65].
    int i = __float2int_rd(xv * 4.0f);
    i = max(-33, min(i, 32));
    float2 ab = p_lane[i * 32];            // lane-private bank pair: conflict-free
    return fmaf(ab.x, xv, ab.y);
}

__device__ __forceinline__ void build_table(const float* __restrict__ table,
                                            float* s_xs, float* s_ys,
                                            float2* s_ab0, float2* s_ab, int t)
{
    if (t < NPTS) {
        s_xs[t] = table[2 * t + 0];
        s_ys[t] = table[2 * t + 1];
    }
    __syncthreads();
    if (t < NREC) {
        float a, b;
        if (t == 0)             { a = 0.0f; b = 0.0f; }   // x < xs[0]
        else if (t == NREC - 1) { a = 0.0f; b = 1.0f; }   // x >= xs[64]
        else {
            int k = t - 1;                                 // segment 0..63
            a = (s_ys[k + 1] - s_ys[k]) / (s_xs[k + 1] - s_xs[k]);
            b = s_ys[k] - a * s_xs[k];
            if (k == NSEG - 1) b += 1.0f;  // fold "+1 for x >= xs[63]"
        }
        s_ab0[t] = make_float2(a, b);
    }
    __syncthreads();
    for (int i = t; i < NREC * 32; i += blockDim.x)
        s_ab[i] = s_ab0[i >> 5];
    __syncthreads();
}

__device__ __forceinline__ float4 eval4(float4 v, const float2* p_lane)
{
    float4 r;
    r.x = eval_rec(v.x, p_lane);
    r.y = eval_rec(v.y, p_lane);
    r.z = eval_rec(v.z, p_lane);
    r.w = eval_rec(v.w, p_lane);
    return r;
}

// Each block handles 1024 float4s (256 threads x 4), front-batched loads.
__global__ void __launch_bounds__(256)
cSigmoid_pwl_kernel(const float4* __restrict__ x4,
                    const float*  __restrict__ table,
                    float4* __restrict__ out4,
                    int n4)
{
    __shared__ float  s_xs[NPTS];
    __shared__ float  s_ys[NPTS];
    __shared__ float2 s_ab0[NREC];
    __shared__ float2 s_ab[NREC * 32];

    int t = threadIdx.x;
    build_table(table, s_xs, s_ys, s_ab0, s_ab, t);

    // lane-private base, offset by +33 records so signed i indexes directly
    const float2* p_lane = s_ab + (t & 31) + 33 * 32;

    int base = blockIdx.x * 1024 + t;
    int i0 = base, i1 = base + 256, i2 = base + 512, i3 = base + 768;

    if (i3 < n4) {
        // fast path: 4 independent load->eval->store chains
        float4 v0 = __ldcs(&x4[i0]);
        float4 v1 = __ldcs(&x4[i1]);
        float4 v2 = __ldcs(&x4[i2]);
        float4 v3 = __ldcs(&x4[i3]);
        __stcs(&out4[i0], eval4(v0, p_lane));
        __stcs(&out4[i1], eval4(v1, p_lane));
        __stcs(&out4[i2], eval4(v2, p_lane));
        __stcs(&out4[i3], eval4(v3, p_lane));
    } else {
        if (i0 < n4) __stcs(&out4[i0], eval4(__ldcs(&x4[i0]), p_lane));
        if (i1 < n4) __stcs(&out4[i1], eval4(__ldcs(&x4[i1]), p_lane));
        if (i2 < n4) __stcs(&out4[i2], eval4(__ldcs(&x4[i2]), p_lane));
    }
}

// Scalar tail (n % 4 != 0); not hit for this shape but kept for generality.
__global__ void cSigmoid_pwl_tail_kernel(const float* __restrict__ x,
                                         const float* __restrict__ table,
                                         float* __restrict__ out,
                                         int start, int n)
{
    __shared__ float  s_xs[NPTS];
    __shared__ float  s_ys[NPTS];
    __shared__ float2 s_ab0[NREC];
    __shared__ float2 s_ab[NREC * 32];

    int t = threadIdx.x;
    build_table(table, s_xs, s_ys, s_ab0, s_ab, t);

    const float2* p_lane = s_ab + (t & 31) + 33 * 32;

    int i = start + blockIdx.x * blockDim.x + t;
    if (i < n) out[i] = eval_rec(x[i], p_lane);
}

extern "C" void kernel_launch(void* const* d_in, const int* in_sizes, int n_in,
                              void* d_out, int out_size)
{
    const float* x     = (const float*)d_in[0];
    const float* table = (const float*)d_in[1];
    float* out         = (float*)d_out;

    int n  = in_sizes[0];
    int n4 = n / 4;

    if (n4 > 0) {
        int blocks = (n4 + 1023) / 1024;
        cSigmoid_pwl_kernel<<<blocks, 256>>>(
            (const float4*)x, table, (float4*)out, n4);
    }

    int tail = n - n4 * 4;
    if (tail > 0) {
        cSigmoid_pwl_tail_kernel<<<1, 256>>>(x, table, out, n4 * 4, n);
    }
}

// round 7
// speedup vs baseline: 1.6823x; 1.0015x over previous
#include <cuda_runtime.h>
#include <cuda_bf16.h>

// Piecewise-linear LUT (65 knots, uniform grid [-8,8], h=0.25).
// Exact searchsorted(side='right') index with NO fixup:
//   idx = floor(4x + 32) = floor(4x) + 32, and 4*x is EXACT in fp32
//   (power-of-two multiply), so __float2int_rd(4x) + 32 is the exact index.
// Per element: FMUL + F2I + 2*IMNMX + conflict-free LDS.64 + FFMA.
// Out-of-range and the reference's "+1 for x >= xs[63]" quirk live in
// sentinel records 0 / 65 and record 64's intercept.
//
// R6: 8 front-batched float4 loads per thread (MLP=8) to fill the LSU/L2
// queues; stores stream out as each batch is evaluated.

#define NPTS 65
#define NSEG 64
#define NREC 66   // record j covers segment j-1; j=0 below-range, j=65 above
#define VPT  8    // float4s per thread

__device__ __forceinline__ float eval_rec(float xv,
                                          const float2* __restrict__ p_lane)
{
    // i = floor(4x), exact. Record index = i + 33, clamped to [0, 65].
    int i = __float2int_rd(xv * 4.0f);
    i = max(-33, min(i, 32));
    float2 ab = p_lane[i * 32];            // lane-private bank pair: conflict-free
    return fmaf(ab.x, xv, ab.y);
}

__device__ __forceinline__ void build_table(const float* __restrict__ table,
                                            float* s_xs, float* s_ys,
                                            float2* s_ab0, float2* s_ab, int t)
{
    if (t < NPTS) {
        s_xs[t] = table[2 * t + 0];
        s_ys[t] = table[2 * t + 1];
    }
    __syncthreads();
    if (t < NREC) {
        float a, b;
        if (t == 0)             { a = 0.0f; b = 0.0f; }   // x < xs[0]
        else if (t == NREC - 1) { a = 0.0f; b = 1.0f; }   // x >= xs[64]
        else {
            int k = t - 1;                                 // segment 0..63
            a = (s_ys[k + 1] - s_ys[k]) / (s_xs[k + 1] - s_xs[k]);
            b = s_ys[k] - a * s_xs[k];
            if (k == NSEG - 1) b += 1.0f;  // fold "+1 for x >= xs[63]"
        }
        s_ab0[t] = make_float2(a, b);
    }
    __syncthreads();
    for (int i = t; i < NREC * 32; i += blockDim.x)
        s_ab[i] = s_ab0[i >> 5];
    __syncthreads();
}

__device__ __forceinline__ float4 eval4(float4 v, const float2* p_lane)
{
    float4 r;
    r.x = eval_rec(v.x, p_lane);
    r.y = eval_rec(v.y, p_lane);
    r.z = eval_rec(v.z, p_lane);
    r.w = eval_rec(v.w, p_lane);
    return r;
}

// Each block handles 256*VPT float4s, loads front-batched for MLP.
__global__ void __launch_bounds__(256)
cSigmoid_pwl_kernel(const float4* __restrict__ x4,
                    const float*  __restrict__ table,
                    float4* __restrict__ out4,
                    int n4)
{
    __shared__ float  s_xs[NPTS];
    __shared__ float  s_ys[NPTS];
    __shared__ float2 s_ab0[NREC];
    __shared__ float2 s_ab[NREC * 32];

    int t = threadIdx.x;
    build_table(table, s_xs, s_ys, s_ab0, s_ab, t);

    // lane-private base, offset by +33 records so signed i indexes directly
    const float2* p_lane = s_ab + (t & 31) + 33 * 32;

    int base = blockIdx.x * (256 * VPT) + t;

    if (base + (VPT - 1) * 256 < n4) {
        // fast path: VPT independent front-batched loads
        float4 v[VPT];
#pragma unroll
        for (int k = 0; k < VPT; k++)
            v[k] = __ldcs(&x4[base + k * 256]);
#pragma unroll
        for (int k = 0; k < VPT; k++)
            __stcs(&out4[base + k * 256], eval4(v[k], p_lane));
    } else {
#pragma unroll
        for (int k = 0; k < VPT; k++) {
            int i = base + k * 256;
            if (i < n4) __stcs(&out4[i], eval4(__ldcs(&x4[i]), p_lane));
        }
    }
}

// Scalar tail (n % 4 != 0); not hit for this shape but kept for generality.
__global__ void cSigmoid_pwl_tail_kernel(const float* __restrict__ x,
                                         const float* __restrict__ table,
                                         float* __restrict__ out,
                                         int start, int n)
{
    __shared__ float  s_xs[NPTS];
    __shared__ float  s_ys[NPTS];
    __shared__ float2 s_ab0[NREC];
    __shared__ float2 s_ab[NREC * 32];

    int t = threadIdx.x;
    build_table(table, s_xs, s_ys, s_ab0, s_ab, t);

    const float2* p_lane = s_ab + (t & 31) + 33 * 32;

    int i = start + blockIdx.x * blockDim.x + t;
    if (i < n) out[i] = eval_rec(x[i], p_lane);
}

extern "C" void kernel_launch(void* const* d_in, const int* in_sizes, int n_in,
                              void* d_out, int out_size)
{
    const float* x     = (const float*)d_in[0];
    const float* table = (const float*)d_in[1];
    float* out         = (float*)d_out;

    int n  = in_sizes[0];
    int n4 = n / 4;

    if (n4 > 0) {
        int per_block = 256 * VPT;
        int blocks = (n4 + per_block - 1) / per_block;
        cSigmoid_pwl_kernel<<<blocks, 256>>>(
            (const float4*)x, table, (float4*)out, n4);
    }

    int tail = n - n4 * 4;
    if (tail > 0) {
        cSigmoid_pwl_tail_kernel<<<1, 256>>>(x, table, out, n4 * 4, n);
    }
}

// round 8
// speedup vs baseline: 1.6960x; 1.0082x over previous
#include <cuda_runtime.h>
#include <cuda_bf16.h>

// Piecewise-linear LUT (65 knots, uniform grid [-8,8], h=0.25).
// Exact searchsorted(side='right') index with NO fixup:
//   idx = floor(4x + 32) = floor(4x) + 32, and 4*x is EXACT in fp32
//   (power-of-two multiply), so __float2int_rd(4x) + 32 is the exact index.
// Per element: FMUL + F2I + 2*IMNMX + conflict-free LDS.64 + FFMA.
// Out-of-range and the reference's "+1 for x >= xs[63]" quirk live in
// sentinel records 0 / 65 and record 64's intercept.
//
// R8: back to VPT=4 (best measured DRAM%), __launch_bounds__(256,8) to pin
// regs<=32 and keep 8 CTAs/SM resident; leaner table build (one sync less).

#define NPTS 65
#define NSEG 64
#define NREC 66   // record j covers segment j-1; j=0 below-range, j=65 above
#define VPT  4    // float4s per thread

__device__ __forceinline__ float eval_rec(float xv,
                                          const float2* __restrict__ p_lane)
{
    // i = floor(4x), exact (power-of-two multiply). Record = i+33 in [0,65].
    int i = __float2int_rd(xv * 4.0f);
    i = max(-33, min(i, 32));
    float2 ab = p_lane[i * 32];            // lane-private bank pair: conflict-free
    return fmaf(ab.x, xv, ab.y);
}

__device__ __forceinline__ void build_table(const float* __restrict__ table,
                                            float2* s_ab0, float2* s_ab, int t)
{
    if (t < NREC) {
        float a, b;
        if (t == 0)             { a = 0.0f; b = 0.0f; }   // x < xs[0]
        else if (t == NREC - 1) { a = 0.0f; b = 1.0f; }   // x >= xs[64]
        else {
            int k = t - 1;                                 // segment 0..63
            float x0 = table[2 * k + 0],     y0 = table[2 * k + 1];
            float x1 = table[2 * k + 2],     y1 = table[2 * k + 3];
            a = (y1 - y0) / (x1 - x0);
            b = y0 - a * x0;
            if (k == NSEG - 1) b += 1.0f;  // fold "+1 for x >= xs[63]"
        }
        s_ab0[t] = make_float2(a, b);
    }
    __syncthreads();
    for (int i = t; i < NREC * 32; i += blockDim.x)
        s_ab[i] = s_ab0[i >> 5];
    __syncthreads();
}

__device__ __forceinline__ float4 eval4(float4 v, const float2* p_lane)
{
    float4 r;
    r.x = eval_rec(v.x, p_lane);
    r.y = eval_rec(v.y, p_lane);
    r.z = eval_rec(v.z, p_lane);
    r.w = eval_rec(v.w, p_lane);
    return r;
}

// Each block handles 256*VPT float4s, loads front-batched for MLP.
__global__ void __launch_bounds__(256, 8)
cSigmoid_pwl_kernel(const float4* __restrict__ x4,
                    const float*  __restrict__ table,
                    float4* __restrict__ out4,
                    int n4)
{
    __shared__ float2 s_ab0[NREC];
    __shared__ float2 s_ab[NREC * 32];

    int t = threadIdx.x;
    build_table(table, s_ab0, s_ab, t);

    // lane-private base, offset by +33 records so signed i indexes directly
    const float2* p_lane = s_ab + (t & 31) + 33 * 32;

    int base = blockIdx.x * (256 * VPT) + t;

    if (base + (VPT - 1) * 256 < n4) {
        // fast path: VPT independent front-batched loads
        float4 v[VPT];
#pragma unroll
        for (int k = 0; k < VPT; k++)
            v[k] = __ldcs(&x4[base + k * 256]);
#pragma unroll
        for (int k = 0; k < VPT; k++)
            __stcs(&out4[base + k * 256], eval4(v[k], p_lane));
    } else {
#pragma unroll
        for (int k = 0; k < VPT; k++) {
            int i = base + k * 256;
            if (i < n4) __stcs(&out4[i], eval4(__ldcs(&x4[i]), p_lane));
        }
    }
}

// Scalar tail (n % 4 != 0); not hit for this shape but kept for generality.
__global__ void cSigmoid_pwl_tail_kernel(const float* __restrict__ x,
                                         const float* __restrict__ table,
                                         float* __restrict__ out,
                                         int start, int n)
{
    __shared__ float2 s_ab0[NREC];
    __shared__ float2 s_ab[NREC * 32];

    int t = threadIdx.x;
    build_table(table, s_ab0, s_ab, t);

    const float2* p_lane = s_ab + (t & 31) + 33 * 32;

    int i = start + blockIdx.x * blockDim.x + t;
    if (i < n) out[i] = eval_rec(x[i], p_lane);
}

extern "C" void kernel_launch(void* const* d_in, const int* in_sizes, int n_in,
                              void* d_out, int out_size)
{
    const float* x     = (const float*)d_in[0];
    const float* table = (const float*)d_in[1];
    float* out         = (float*)d_out;

    int n  = in_sizes[0];
    int n4 = n / 4;

    if (n4 > 0) {
        int per_block = 256 * VPT;
        int blocks = (n4 + per_block - 1) / per_block;
        cSigmoid_pwl_kernel<<<blocks, 256>>>(
            (const float4*)x, table, (float4*)out, n4);
    }

    int tail = n - n4 * 4;
    if (tail > 0) {
        cSigmoid_pwl_tail_kernel<<<1, 256>>>(x, table, out, n4 * 4, n);
    }
}

// round 9
// speedup vs baseline: 1.6967x; 1.0004x over previous
#include <cuda_runtime.h>
#include <cuda_bf16.h>

// Piecewise-linear LUT (65 knots, uniform grid [-8,8], h=0.25).
// Exact searchsorted(side='right') index with NO fixup:
//   idx = floor(4x + 32) = floor(4x) + 32, and 4*x is EXACT in fp32
//   (power-of-two multiply), so __float2int_rd(4x) + 32 is the exact index.
// Per element: FMUL + F2I + 2*IMNMX + conflict-free LDS.64 + FFMA.
// Out-of-range and the reference's "+1 for x >= xs[63]" quirk live in
// sentinel records 0 / 65 and record 64's intercept.
//
// R9: __ldcg loads (skip L1 — pure streaming), 512-thread blocks (half the
// table-build prologues) at the same occupancy; VPT=4 per thread (proven).

#define NPTS 65
#define NSEG 64
#define NREC 66   // record j covers segment j-1; j=0 below-range, j=65 above
#define VPT  4    // float4s per thread
#define TPB  512

__device__ __forceinline__ float eval_rec(float xv,
                                          const float2* __restrict__ p_lane)
{
    // i = floor(4x), exact (power-of-two multiply). Record = i+33 in [0,65].
    int i = __float2int_rd(xv * 4.0f);
    i = max(-33, min(i, 32));
    float2 ab = p_lane[i * 32];            // lane-private bank pair: conflict-free
    return fmaf(ab.x, xv, ab.y);
}

__device__ __forceinline__ void build_table(const float* __restrict__ table,
                                            float2* s_ab0, float2* s_ab, int t)
{
    if (t < NREC) {
        float a, b;
        if (t == 0)             { a = 0.0f; b = 0.0f; }   // x < xs[0]
        else if (t == NREC - 1) { a = 0.0f; b = 1.0f; }   // x >= xs[64]
        else {
            int k = t - 1;                                 // segment 0..63
            float x0 = table[2 * k + 0],     y0 = table[2 * k + 1];
            float x1 = table[2 * k + 2],     y1 = table[2 * k + 3];
            a = (y1 - y0) / (x1 - x0);
            b = y0 - a * x0;
            if (k == NSEG - 1) b += 1.0f;  // fold "+1 for x >= xs[63]"
        }
        s_ab0[t] = make_float2(a, b);
    }
    __syncthreads();
    for (int i = t; i < NREC * 32; i += blockDim.x)
        s_ab[i] = s_ab0[i >> 5];
    __syncthreads();
}

__device__ __forceinline__ float4 eval4(float4 v, const float2* p_lane)
{
    float4 r;
    r.x = eval_rec(v.x, p_lane);
    r.y = eval_rec(v.y, p_lane);
    r.z = eval_rec(v.z, p_lane);
    r.w = eval_rec(v.w, p_lane);
    return r;
}

// Each block handles TPB*VPT float4s, loads front-batched for MLP.
__global__ void __launch_bounds__(TPB, 4)
cSigmoid_pwl_kernel(const float4* __restrict__ x4,
                    const float*  __restrict__ table,
                    float4* __restrict__ out4,
                    int n4)
{
    __shared__ float2 s_ab0[NREC];
    __shared__ float2 s_ab[NREC * 32];

    int t = threadIdx.x;
    build_table(table, s_ab0, s_ab, t);

    // lane-private base, offset by +33 records so signed i indexes directly
    const float2* p_lane = s_ab + (t & 31) + 33 * 32;

    int base = blockIdx.x * (TPB * VPT) + t;

    if (base + (VPT - 1) * TPB < n4) {
        // fast path: VPT independent front-batched loads (L1-bypassed)
        float4 v[VPT];
#pragma unroll
        for (int k = 0; k < VPT; k++)
            v[k] = __ldcg(&x4[base + k * TPB]);
#pragma unroll
        for (int k = 0; k < VPT; k++)
            __stcs(&out4[base + k * TPB], eval4(v[k], p_lane));
    } else {
#pragma unroll
        for (int k = 0; k < VPT; k++) {
            int i = base + k * TPB;
            if (i < n4) __stcs(&out4[i], eval4(__ldcg(&x4[i]), p_lane));
        }
    }
}

// Scalar tail (n % 4 != 0); not hit for this shape but kept for generality.
__global__ void cSigmoid_pwl_tail_kernel(const float* __restrict__ x,
                                         const float* __restrict__ table,
                                         float* __restrict__ out,
                                         int start, int n)
{
    __shared__ float2 s_ab0[NREC];
    __shared__ float2 s_ab[NREC * 32];

    int t = threadIdx.x;
    build_table(table, s_ab0, s_ab, t);

    const float2* p_lane = s_ab + (t & 31) + 33 * 32;

    int i = start + blockIdx.x * blockDim.x + t;
    if (i < n) out[i] = eval_rec(x[i], p_lane);
}

extern "C" void kernel_launch(void* const* d_in, const int* in_sizes, int n_in,
                              void* d_out, int out_size)
{
    const float* x     = (const float*)d_in[0];
    const float* table = (const float*)d_in[1];
    float* out         = (float*)d_out;

    int n  = in_sizes[0];
    int n4 = n / 4;

    if (n4 > 0) {
        int per_block = TPB * VPT;
        int blocks = (n4 + per_block - 1) / per_block;
        cSigmoid_pwl_kernel<<<blocks, TPB>>>(
            (const float4*)x, table, (float4*)out, n4);
    }

    int tail = n - n4 * 4;
    if (tail > 0) {
        cSigmoid_pwl_tail_kernel<<<1, 256>>>(x, table, out, n4 * 4, n);
    }
}